// round 4
// baseline (speedup 1.0000x reference)
#include <cuda_runtime.h>
#include <cstdint>

// Problem constants (fixed shapes for this problem)
#define Bc 8
#define Hc 1024
#define Ec 512
#define Vc 32000
#define Tc 100
#define KVc 1536   // H + E   (x_v width)
#define KKc 2560   // 2H + E  (x_k width)

#define GRID_MAIN 296          // 2 blocks per SM on 148 SMs, single wave
// 8000 tiles = 296*27 + 8 -> first 8 blocks take 28 tiles, rest 27
#define MAXW 112               // max vocab words per block (28 tiles * 4)

// Dynamic smem layout (floats):
//   xs     [8 * 2560]  = 20480   x_k rows (x_v is the 1536-prefix)
//   scnt   [8 * 112]   = 896     (int) topic counts, block-local
//   sekval [8 * 112]   = 896     e_k values, block-local
//   sm_ps  [8 * 8]     = 64      per-warp batch sums
#define SM_FLOATS (20480 + 896 + 896 + 64)
#define SM_BYTES  (SM_FLOATS * 4)

// Scratch (device global; no runtime allocation allowed)
__device__ float g_psum[GRID_MAIN * Bc];       // per-BLOCK partial softmax sums

// ---------------------------------------------------------------------------
// Main kernel: fused topic-gate + GEMV + tanh + exp + block partial sums.
// Phase 0: fill xs = [output|input|context] per batch; zero gate arrays.
// Phase 1: warp w handles batch b=w: scan its 100 topic ids; for ids in this
//          block's vocab range, count occurrences (smem atomics, exact) and
//          compute e_k = x_k . W_K[id] + b_K[id] (warp-wide dot, ~2.8/block).
// Phase 2: GEMV over W_V tiles (4 rows x 8 batches per warp-tile), butterfly
//          transpose-reduce, gate from smem, tanh/exp, store, partial sums.
// ---------------------------------------------------------------------------
__global__ void __launch_bounds__(256, 2) main_kernel(const float* __restrict__ outp,
                                                      const float* __restrict__ inp,
                                                      const float* __restrict__ ctx,
                                                      const int*   __restrict__ topics,
                                                      const float* __restrict__ WV,
                                                      const float* __restrict__ bV,
                                                      const float* __restrict__ WK,
                                                      const float* __restrict__ bK,
                                                      float* __restrict__ out) {
    extern __shared__ float smem[];
    float* xs     = smem;                      // [8][2560]
    int*   scnt   = (int*)(smem + 20480);      // [8][112]
    float* sekval = smem + 20480 + 896;        // [8][112]
    float* sm_ps  = smem + 20480 + 1792;       // [8][8]

    int tid  = threadIdx.x;
    int warp = tid >> 5;
    int lane = tid & 31;

    int blk   = blockIdx.x;
    int tbase = blk * 27 + (blk < 8 ? blk : 8);
    int tcnt  = 27 + (blk < 8 ? 1 : 0);
    int wlo   = tbase * 4;
    int whi   = wlo + tcnt * 4;

    // ---- Phase 0: cooperative fill of x_k, zero gate arrays ----
    for (int i = tid; i < (Bc * KKc) / 4; i += 256) {
        int fi = i * 4;
        int b = fi / KKc;
        int c = fi % KKc;
        float4 v;
        if (c < Hc)            v = *(const float4*)(outp + b * Hc + c);
        else if (c < Hc + Ec)  v = *(const float4*)(inp  + b * Ec + (c - Hc));
        else                   v = *(const float4*)(ctx  + b * Hc + (c - Hc - Ec));
        *(float4*)(xs + fi) = v;
    }
    for (int i = tid; i < Bc * MAXW; i += 256) {
        scnt[i] = 0;
        sekval[i] = 0.f;
    }
    __syncthreads();

    // ---- Phase 1: per-batch topic scan + e_k gather for in-range words ----
    {
        int b = warp;   // 8 warps, 8 batches
        const float* xb = xs + b * KKc;
        #pragma unroll
        for (int i = 0; i < 4; i++) {
            int t = i * 32 + lane;
            int w = (t < Tc) ? topics[b * Tc + t] : 0;
            bool found = (w != 0) && (w >= wlo) && (w < whi);
            unsigned m = __ballot_sync(0xffffffffu, found);
            while (m) {
                int src = __ffs(m) - 1;
                m &= m - 1;
                int ww = __shfl_sync(0xffffffffu, w, src);
                // warp-wide dot: x_k[b] . W_K[ww]
                const float* wrow = WK + (size_t)ww * KKc;
                float s = 0.f;
                #pragma unroll 4
                for (int c = lane * 4; c < KKc; c += 128) {
                    float4 wv = *(const float4*)(wrow + c);
                    float4 xv = *(const float4*)(xb + c);
                    s += wv.x * xv.x + wv.y * xv.y + wv.z * xv.z + wv.w * xv.w;
                }
                #pragma unroll
                for (int h = 16; h >= 1; h >>= 1) s += __shfl_xor_sync(0xffffffffu, s, h);
                if (lane == 0) {
                    atomicAdd(&scnt[b * MAXW + (ww - wlo)], 1);
                    sekval[b * MAXW + (ww - wlo)] = s + __ldg(bK + ww);
                }
            }
        }
    }
    __syncthreads();

    // ---- Phase 2: W_V GEMV ----
    int b = lane & 7;
    int r = lane >> 3;
    float lsum = 0.f;

    #pragma unroll 1
    for (int k = warp; k < tcnt; k += 8) {
        int tile = tbase + k;
        int w0 = tile * 4;
        float acc[32];
        #pragma unroll
        for (int j = 0; j < 32; j++) acc[j] = 0.f;

        const float* Wp = WV + (size_t)w0 * KVc + lane * 4;

        // double-buffered W loads
        float4 wc0 = *(const float4*)(Wp);
        float4 wc1 = *(const float4*)(Wp + KVc);
        float4 wc2 = *(const float4*)(Wp + 2 * KVc);
        float4 wc3 = *(const float4*)(Wp + 3 * KVc);

        #pragma unroll 2
        for (int it = 0; it < 12; it++) {
            float4 wn0, wn1, wn2, wn3;
            if (it < 11) {
                const float* Pn = Wp + (it + 1) * 128;
                wn0 = *(const float4*)(Pn);
                wn1 = *(const float4*)(Pn + KVc);
                wn2 = *(const float4*)(Pn + 2 * KVc);
                wn3 = *(const float4*)(Pn + 3 * KVc);
            }
            int xb = it * 128 + lane * 4;
            #pragma unroll
            for (int bb = 0; bb < 8; bb++) {
                float4 xv = *(const float4*)(xs + bb * KKc + xb);
                acc[0 * 8 + bb] = fmaf(wc0.x, xv.x, acc[0 * 8 + bb]);
                acc[0 * 8 + bb] = fmaf(wc0.y, xv.y, acc[0 * 8 + bb]);
                acc[0 * 8 + bb] = fmaf(wc0.z, xv.z, acc[0 * 8 + bb]);
                acc[0 * 8 + bb] = fmaf(wc0.w, xv.w, acc[0 * 8 + bb]);
                acc[1 * 8 + bb] = fmaf(wc1.x, xv.x, acc[1 * 8 + bb]);
                acc[1 * 8 + bb] = fmaf(wc1.y, xv.y, acc[1 * 8 + bb]);
                acc[1 * 8 + bb] = fmaf(wc1.z, xv.z, acc[1 * 8 + bb]);
                acc[1 * 8 + bb] = fmaf(wc1.w, xv.w, acc[1 * 8 + bb]);
                acc[2 * 8 + bb] = fmaf(wc2.x, xv.x, acc[2 * 8 + bb]);
                acc[2 * 8 + bb] = fmaf(wc2.y, xv.y, acc[2 * 8 + bb]);
                acc[2 * 8 + bb] = fmaf(wc2.z, xv.z, acc[2 * 8 + bb]);
                acc[2 * 8 + bb] = fmaf(wc2.w, xv.w, acc[2 * 8 + bb]);
                acc[3 * 8 + bb] = fmaf(wc3.x, xv.x, acc[3 * 8 + bb]);
                acc[3 * 8 + bb] = fmaf(wc3.y, xv.y, acc[3 * 8 + bb]);
                acc[3 * 8 + bb] = fmaf(wc3.z, xv.z, acc[3 * 8 + bb]);
                acc[3 * 8 + bb] = fmaf(wc3.w, xv.w, acc[3 * 8 + bb]);
            }
            wc0 = wn0; wc1 = wn1; wc2 = wn2; wc3 = wn3;
        }

        // butterfly transpose-reduce: 31 shuffles; lane l ends with sum of acc[l]
        #pragma unroll
        for (int h = 16; h >= 1; h >>= 1) {
            #pragma unroll
            for (int j = 0; j < h; j++) {
                float lo = acc[j];
                float hi = acc[j + h];
                float mine = (lane & h) ? hi : lo;
                float send = (lane & h) ? lo : hi;
                float recv = __shfl_xor_sync(0xffffffffu, send, h);
                acc[j] = mine + recv;
            }
        }

        int w = w0 + r;
        int li = b * MAXW + (w - wlo);
        float ev = acc[0] + __ldg(bV + w);
        int cnt = scnt[li];
        float en = (cnt == 0) ? ev : (float)cnt * sekval[li];
        en = tanhf(en);
        float p = __expf(en);
        out[b * Vc + w] = p;
        lsum += p;
    }

    // lanes {l, l^8, l^16, l^24} share batch b = l&7 -> combine, lane<8 writes
    lsum += __shfl_xor_sync(0xffffffffu, lsum, 8);
    lsum += __shfl_xor_sync(0xffffffffu, lsum, 16);
    if (lane < 8) sm_ps[warp * 8 + b] = lsum;
    __syncthreads();

    // block-level deterministic combine: 8 warps -> one value per batch
    if (tid < 8) {
        float s = 0.f;
        #pragma unroll
        for (int wv = 0; wv < 8; wv++) s += sm_ps[wv * 8 + tid];
        g_psum[blockIdx.x * 8 + tid] = s;
    }
}

// ---------------------------------------------------------------------------
// Norm kernel: fused reduce + normalize.
// grid (125, 8), 256 threads. Each block redundantly (deterministically)
// reduces the 296 per-block partials for its batch (L2-resident), then
// normalizes its 256-element slice.
// ---------------------------------------------------------------------------
__global__ void norm_kernel(float* __restrict__ out) {
    int b = blockIdx.y;
    int tid = threadIdx.x;
    __shared__ float ssum[8];
    __shared__ float srinv;

    float s = 0.f;
    if (tid < GRID_MAIN)       s += g_psum[tid * 8 + b];
    if (tid + 256 < GRID_MAIN) s += g_psum[(tid + 256) * 8 + b];
    #pragma unroll
    for (int h = 16; h >= 1; h >>= 1) s += __shfl_xor_sync(0xffffffffu, s, h);
    if ((tid & 31) == 0) ssum[tid >> 5] = s;
    __syncthreads();
    if (tid == 0) {
        float t = 0.f;
        #pragma unroll
        for (int w = 0; w < 8; w++) t += ssum[w];
        srinv = 1.0f / t;
    }
    __syncthreads();

    int i = blockIdx.x * 256 + tid;   // 125*256 == 32000 exactly
    out[b * Vc + i] *= srinv;
}

// ---------------------------------------------------------------------------
// Launch (2 kernels)
// Input order: output, input_step, context, topic_indexs, [topic_length],
//              W_V, b_V, W_K, b_K
// ---------------------------------------------------------------------------
extern "C" void kernel_launch(void* const* d_in, const int* in_sizes, int n_in,
                              void* d_out, int out_size) {
    const float* outp   = (const float*)d_in[0];
    const float* inp    = (const float*)d_in[1];
    const float* ctx    = (const float*)d_in[2];
    const int*   topics = (const int*)d_in[3];

    int base = 4;
    if (n_in >= 9 && in_sizes[4] <= 4) base = 5;   // skip topic_length scalar

    const float* WV = (const float*)d_in[base + 0];
    const float* bV = (const float*)d_in[base + 1];
    const float* WK = (const float*)d_in[base + 2];
    const float* bK = (const float*)d_in[base + 3];
    float* out = (float*)d_out;

    cudaFuncSetAttribute(main_kernel, cudaFuncAttributeMaxDynamicSharedMemorySize, SM_BYTES);

    main_kernel<<<GRID_MAIN, 256, SM_BYTES>>>(outp, inp, ctx, topics, WV, bV, WK, bK, out);
    norm_kernel<<<dim3(Vc / 256, Bc), 256>>>(out);
}

// round 5
// speedup vs baseline: 1.2487x; 1.2487x over previous
#include <cuda_runtime.h>
#include <cstdint>

// Problem constants (fixed shapes for this problem)
#define Bc 8
#define Hc 1024
#define Ec 512
#define Vc 32000
#define Tc 100
#define KVc 1536   // H + E   (x_v width)
#define KKc 2560   // 2H + E  (x_k width)

#define GRID_MAIN 296          // 2 blocks per SM on 148 SMs, single wave
// 8000 tiles = 296*27 + 8 -> first 8 blocks take 28 tiles, rest 27

// Scratch (device globals; zero-initialized at module load, no runtime alloc)
__device__ int   g_cnt[Bc * Vc];               // topic word counts (kept zero between runs)
__device__ float g_ekval[Bc * Vc];             // e_k values (valid only where cnt>0)
__device__ float g_psum[GRID_MAIN * Bc];       // per-BLOCK partial softmax sums

// ---------------------------------------------------------------------------
// Kernel 1: count topic words + compute e_k for each (b, topic word) pair.
// 4 warps per pair (each warp covers 640 of 2560 columns -> 5 float4/lane,
// fully unrolled => 10 loads in flight), smem combine. 800 pairs -> 400
// blocks x 256 threads (2 pairs per block).
// g_cnt is guaranteed all-zero on entry (zero-init + cleanup in norm kernel).
// ---------------------------------------------------------------------------
__global__ void __launch_bounds__(256) count_ek_kernel(const int*   __restrict__ topics,
                                                       const float* __restrict__ outp,
                                                       const float* __restrict__ inp,
                                                       const float* __restrict__ ctx,
                                                       const float* __restrict__ WK,
                                                       const float* __restrict__ bK) {
    __shared__ float part[2][4];

    int tid  = threadIdx.x;
    int warp = tid >> 5;
    int lane = tid & 31;
    int lp   = warp >> 2;        // local pair 0/1
    int q    = warp & 3;         // quarter of the 2560-dot
    int pair = blockIdx.x * 2 + lp;

    int b   = pair / Tc;
    int idx = topics[pair];

    float s = 0.f;
    if (idx != 0) {
        const float* wrow = WK + (size_t)idx * KKc + q * 640;
        int cbase = q * 640 + lane * 4;
        #pragma unroll
        for (int i = 0; i < 5; i++) {
            int cc = cbase + i * 128;
            float4 wv = *(const float4*)(wrow + lane * 4 + i * 128);
            float4 xv;
            if (cc < Hc)            xv = *(const float4*)(outp + b * Hc + cc);
            else if (cc < Hc + Ec)  xv = *(const float4*)(inp  + b * Ec + (cc - Hc));
            else                    xv = *(const float4*)(ctx  + b * Hc + (cc - Hc - Ec));
            s += wv.x * xv.x + wv.y * xv.y + wv.z * xv.z + wv.w * xv.w;
        }
        #pragma unroll
        for (int h = 16; h >= 1; h >>= 1) s += __shfl_xor_sync(0xffffffffu, s, h);
    }
    if (lane == 0) part[lp][q] = s;
    __syncthreads();

    // one thread per pair finalizes
    if (tid < 2) {
        int p2 = blockIdx.x * 2 + tid;
        int b2 = p2 / Tc;
        int i2 = topics[p2];
        if (i2 != 0) {
            float e = part[tid][0] + part[tid][1] + part[tid][2] + part[tid][3];
            atomicAdd(&g_cnt[b2 * Vc + i2], 1);
            g_ekval[b2 * Vc + i2] = e + bK[i2];   // duplicates write identical values
        }
    }
}

// ---------------------------------------------------------------------------
// Kernel 2: main GEMV + gate + tanh + exp + block-level partial sums.
// (identical to the proven R3 version: 48 KB static smem, 2 blocks/SM)
// ---------------------------------------------------------------------------
__global__ void __launch_bounds__(256, 2) main_kernel(const float* __restrict__ outp,
                                                      const float* __restrict__ inp,
                                                      const float* __restrict__ WV,
                                                      const float* __restrict__ bV,
                                                      float* __restrict__ out) {
    __shared__ float xs[Bc * KVc];   // 49152 bytes (exactly 48 KB)
    __shared__ float sm_ps[8 * Bc];  // per-warp batch sums

    // cooperative fill of x_v = concat(output, input_step) per batch
    for (int i = threadIdx.x; i < (Bc * KVc) / 4; i += blockDim.x) {
        int fi = i * 4;
        int b = fi / KVc;
        int c = fi % KVc;
        float4 v;
        if (c < Hc) v = *(const float4*)(outp + b * Hc + c);
        else        v = *(const float4*)(inp  + b * Ec + (c - Hc));
        *(float4*)(xs + fi) = v;
    }
    __syncthreads();

    int warp = threadIdx.x >> 5;
    int lane = threadIdx.x & 31;
    int b = lane & 7;
    int r = lane >> 3;
    float lsum = 0.f;

    int blk = blockIdx.x;
    int tbase = blk * 27 + (blk < 8 ? blk : 8);
    int tcnt  = 27 + (blk < 8 ? 1 : 0);

    #pragma unroll 1
    for (int k = warp; k < tcnt; k += 8) {
        int tile = tbase + k;
        int w0 = tile * 4;
        float acc[32];
        #pragma unroll
        for (int j = 0; j < 32; j++) acc[j] = 0.f;

        const float* Wp = WV + (size_t)w0 * KVc + lane * 4;

        // double-buffered W loads
        float4 wc0 = *(const float4*)(Wp);
        float4 wc1 = *(const float4*)(Wp + KVc);
        float4 wc2 = *(const float4*)(Wp + 2 * KVc);
        float4 wc3 = *(const float4*)(Wp + 3 * KVc);

        #pragma unroll 2
        for (int it = 0; it < 12; it++) {
            float4 wn0, wn1, wn2, wn3;
            if (it < 11) {
                const float* Pn = Wp + (it + 1) * 128;
                wn0 = *(const float4*)(Pn);
                wn1 = *(const float4*)(Pn + KVc);
                wn2 = *(const float4*)(Pn + 2 * KVc);
                wn3 = *(const float4*)(Pn + 3 * KVc);
            }
            int xb = it * 128 + lane * 4;
            #pragma unroll
            for (int bb = 0; bb < 8; bb++) {
                float4 xv = *(const float4*)(xs + bb * KVc + xb);
                acc[0 * 8 + bb] = fmaf(wc0.x, xv.x, acc[0 * 8 + bb]);
                acc[0 * 8 + bb] = fmaf(wc0.y, xv.y, acc[0 * 8 + bb]);
                acc[0 * 8 + bb] = fmaf(wc0.z, xv.z, acc[0 * 8 + bb]);
                acc[0 * 8 + bb] = fmaf(wc0.w, xv.w, acc[0 * 8 + bb]);
                acc[1 * 8 + bb] = fmaf(wc1.x, xv.x, acc[1 * 8 + bb]);
                acc[1 * 8 + bb] = fmaf(wc1.y, xv.y, acc[1 * 8 + bb]);
                acc[1 * 8 + bb] = fmaf(wc1.z, xv.z, acc[1 * 8 + bb]);
                acc[1 * 8 + bb] = fmaf(wc1.w, xv.w, acc[1 * 8 + bb]);
                acc[2 * 8 + bb] = fmaf(wc2.x, xv.x, acc[2 * 8 + bb]);
                acc[2 * 8 + bb] = fmaf(wc2.y, xv.y, acc[2 * 8 + bb]);
                acc[2 * 8 + bb] = fmaf(wc2.z, xv.z, acc[2 * 8 + bb]);
                acc[2 * 8 + bb] = fmaf(wc2.w, xv.w, acc[2 * 8 + bb]);
                acc[3 * 8 + bb] = fmaf(wc3.x, xv.x, acc[3 * 8 + bb]);
                acc[3 * 8 + bb] = fmaf(wc3.y, xv.y, acc[3 * 8 + bb]);
                acc[3 * 8 + bb] = fmaf(wc3.z, xv.z, acc[3 * 8 + bb]);
                acc[3 * 8 + bb] = fmaf(wc3.w, xv.w, acc[3 * 8 + bb]);
            }
            wc0 = wn0; wc1 = wn1; wc2 = wn2; wc3 = wn3;
        }

        // butterfly transpose-reduce: 31 shuffles; lane l ends with sum of acc[l]
        #pragma unroll
        for (int h = 16; h >= 1; h >>= 1) {
            #pragma unroll
            for (int j = 0; j < h; j++) {
                float lo = acc[j];
                float hi = acc[j + h];
                float mine = (lane & h) ? hi : lo;
                float send = (lane & h) ? lo : hi;
                float recv = __shfl_xor_sync(0xffffffffu, send, h);
                acc[j] = mine + recv;
            }
        }

        int w = w0 + r;
        float ev = acc[0] + __ldg(bV + w);
        int cnt = g_cnt[b * Vc + w];
        float en = (cnt == 0) ? ev : (float)cnt * g_ekval[b * Vc + w];
        en = tanhf(en);
        float p = __expf(en);
        out[b * Vc + w] = p;
        lsum += p;
    }

    // lanes {l, l^8, l^16, l^24} share batch b = l&7 -> combine, lane<8 writes
    lsum += __shfl_xor_sync(0xffffffffu, lsum, 8);
    lsum += __shfl_xor_sync(0xffffffffu, lsum, 16);
    if (lane < 8) sm_ps[warp * 8 + b] = lsum;
    __syncthreads();

    // block-level deterministic combine: 8 warps -> one value per batch
    if (threadIdx.x < 8) {
        float s = 0.f;
        #pragma unroll
        for (int wv = 0; wv < 8; wv++) s += sm_ps[wv * 8 + threadIdx.x];
        g_psum[blockIdx.x * 8 + threadIdx.x] = s;
    }
}

// ---------------------------------------------------------------------------
// Kernel 3: fused reduce + normalize + g_cnt cleanup.
// grid (125, 8), 256 threads. Each block redundantly (deterministically)
// reduces the 296 per-block partials for its batch (L2-resident), then
// normalizes its 256-element slice. Blocks at x==0 re-zero the g_cnt entries
// touched by this run, restoring the all-zero invariant for the next replay.
// ---------------------------------------------------------------------------
__global__ void norm_kernel(float* __restrict__ out, const int* __restrict__ topics) {
    int b = blockIdx.y;
    int tid = threadIdx.x;
    __shared__ float ssum[8];
    __shared__ float srinv;

    float s = 0.f;
    if (tid < GRID_MAIN)       s += g_psum[tid * 8 + b];
    if (tid + 256 < GRID_MAIN) s += g_psum[(tid + 256) * 8 + b];
    #pragma unroll
    for (int h = 16; h >= 1; h >>= 1) s += __shfl_xor_sync(0xffffffffu, s, h);
    if ((tid & 31) == 0) ssum[tid >> 5] = s;
    __syncthreads();
    if (tid == 0) {
        float t = 0.f;
        #pragma unroll
        for (int w = 0; w < 8; w++) t += ssum[w];
        srinv = 1.0f / t;
    }
    __syncthreads();

    // cleanup: restore g_cnt to all-zero (indices touched this run only)
    if (blockIdx.x == 0) {
        for (int t = tid; t < Tc; t += 256)
            g_cnt[b * Vc + topics[b * Tc + t]] = 0;
    }

    int i = blockIdx.x * 256 + tid;   // 125*256 == 32000 exactly
    out[b * Vc + i] *= srinv;
}

// ---------------------------------------------------------------------------
// Launch (3 kernels)
// Input order: output, input_step, context, topic_indexs, [topic_length],
//              W_V, b_V, W_K, b_K
// ---------------------------------------------------------------------------
extern "C" void kernel_launch(void* const* d_in, const int* in_sizes, int n_in,
                              void* d_out, int out_size) {
    const float* outp   = (const float*)d_in[0];
    const float* inp    = (const float*)d_in[1];
    const float* ctx    = (const float*)d_in[2];
    const int*   topics = (const int*)d_in[3];

    int base = 4;
    if (n_in >= 9 && in_sizes[4] <= 4) base = 5;   // skip topic_length scalar

    const float* WV = (const float*)d_in[base + 0];
    const float* bV = (const float*)d_in[base + 1];
    const float* WK = (const float*)d_in[base + 2];
    const float* bK = (const float*)d_in[base + 3];
    float* out = (float*)d_out;

    count_ek_kernel<<<(Bc * Tc) / 2, 256>>>(topics, outp, inp, ctx, WK, bK);
    main_kernel<<<GRID_MAIN, 256>>>(outp, inp, WV, bV, out);
    norm_kernel<<<dim3(Vc / 256, Bc), 256>>>(out, topics);
}